// round 1
// baseline (speedup 1.0000x reference)
#include <cuda_runtime.h>

#define H     128
#define TM    128
#define KT    16
#define HPAD  136
#define MAXE  1000000

// ---------------- device globals (scratch; no allocations allowed) ----------
__device__ int d_count[6];
__device__ int d_off[8];
__device__ int d_cur[6];
__device__ int d_perm[MAXE];

// combo LUT over (gs*3+ge): COMBOS=[(0,0),(0,1),(0,2),(1,1),(1,2),(2,2)]
__constant__ int c_lut[9] = {0, 1, 2, -1, 3, 4, -1, -1, 5};

// ---------------- f32x2 packed math helpers ---------------------------------
__device__ __forceinline__ unsigned long long pack2(float lo, float hi) {
    unsigned long long r;
    asm("mov.b64 %0, {%1, %2};" : "=l"(r) : "f"(lo), "f"(hi));
    return r;
}
__device__ __forceinline__ void unpack2(unsigned long long v, float& lo, float& hi) {
    asm("mov.b64 {%0, %1}, %2;" : "=f"(lo), "=f"(hi) : "l"(v));
}
__device__ __forceinline__ void ffma2(unsigned long long& d, unsigned long long a,
                                      unsigned long long b) {
    asm("fma.rn.f32x2 %0, %1, %2, %0;" : "+l"(d) : "l"(a), "l"(b));
}

// ---------------- bucketing kernels ------------------------------------------
__global__ void k_reset() {
    if (threadIdx.x < 6) { d_count[threadIdx.x] = 0; d_cur[threadIdx.x] = 0; }
}

__global__ void k_classify(const int* __restrict__ ei, const int* __restrict__ vol,
                           float* __restrict__ out, int E) {
    int i = blockIdx.x * blockDim.x + threadIdx.x;
    if (i >= E) return;
    out[i] = 0.f;  // default (covers gs>ge edges; valid edges overwritten later)
    int gs = vol[ei[i]] / 3;
    int ge = vol[ei[E + i]] / 3;
    int c = c_lut[gs * 3 + ge];
    if (c >= 0) atomicAdd(&d_count[c], 1);
}

__global__ void k_prefix() {
    if (threadIdx.x == 0) {
        int o = 0;
        for (int c = 0; c < 6; c++) { d_off[c] = o; o += d_count[c]; }
        d_off[6] = o;
    }
}

__global__ void k_scatter(const int* __restrict__ ei, const int* __restrict__ vol, int E) {
    int i = blockIdx.x * blockDim.x + threadIdx.x;
    if (i >= E) return;
    int gs = vol[ei[i]] / 3;
    int ge = vol[ei[E + i]] / 3;
    int c = c_lut[gs * 3 + ge];
    if (c >= 0) {
        int p = d_off[c] + atomicAdd(&d_cur[c], 1);
        d_perm[p] = i;
    }
}

// ---------------- fused expert MLP kernel ------------------------------------
struct SMem {
    float As[KT][TM];      // k-major A staging (layer1)
    float Ws[KT][H];       // weight k-tile
    float h[TM][HPAD];     // activations (padded rows to dodge bank conflicts)
    int   offs[3][TM];     // xs/xe/e row base offsets (in floats)
    int   rowi[TM];        // global edge index per row
};

__device__ __forceinline__ void ln_relu_row(SMem& sm, const float* __restrict__ g,
                                            const float* __restrict__ be, int tid) {
    if (tid >= TM) return;
    float* row = sm.h[tid];
    float s = 0.f, ss = 0.f;
#pragma unroll
    for (int q = 0; q < 32; q++) {
        float4 v = *reinterpret_cast<float4*>(row + q * 4);
        s  += v.x + v.y + v.z + v.w;
        ss += v.x * v.x + v.y * v.y + v.z * v.z + v.w * v.w;
    }
    float mu  = s * (1.f / 128.f);
    float var = ss * (1.f / 128.f) - mu * mu;
    float inv = rsqrtf(var + 1e-5f);
#pragma unroll
    for (int q = 0; q < 32; q++) {
        float4 v  = *reinterpret_cast<float4*>(row + q * 4);
        float4 gq = *reinterpret_cast<const float4*>(g + q * 4);
        float4 bq = *reinterpret_cast<const float4*>(be + q * 4);
        v.x = fmaxf((v.x - mu) * inv * gq.x + bq.x, 0.f);
        v.y = fmaxf((v.y - mu) * inv * gq.y + bq.y, 0.f);
        v.z = fmaxf((v.z - mu) * inv * gq.z + bq.z, 0.f);
        v.w = fmaxf((v.w - mu) * inv * gq.w + bq.w, 0.f);
        *reinterpret_cast<float4*>(row + q * 4) = v;
    }
}

__global__ __launch_bounds__(256) void k_decode(
    const float* __restrict__ x, const float* __restrict__ e, const int* __restrict__ ei,
    const float* __restrict__ W1, const float* __restrict__ b1,
    const float* __restrict__ g1, const float* __restrict__ be1,
    const float* __restrict__ W2, const float* __restrict__ b2,
    const float* __restrict__ g2, const float* __restrict__ be2,
    const float* __restrict__ W3, const float* __restrict__ b3,
    float* __restrict__ out, int E) {
    extern __shared__ char smraw[];
    SMem& sm = *reinterpret_cast<SMem*>(smraw);

    const int c     = blockIdx.y;
    const int off_c = d_off[c];
    const int count = d_off[c + 1] - off_c;
    const int m0    = blockIdx.x * TM;
    if (m0 >= count) return;
    const int m   = min(TM, count - m0);
    const int tid = threadIdx.x;

    if (tid < TM) {
        int rr = (tid < m) ? tid : 0;
        int i  = d_perm[off_c + m0 + rr];
        sm.rowi[tid] = i;
        int s = ei[i];
        int t = ei[E + i];
        sm.offs[0][tid] = s * H;
        sm.offs[1][tid] = t * H;
        sm.offs[2][tid] = i * H;
    }
    __syncthreads();

    const int ty = tid >> 4;
    const int tx = tid & 15;
    const int ar = tid >> 1;         // A-load row
    const int ak = (tid & 1) * 8;    // A-load k offset
    const int wk = tid >> 4;         // W-load k row
    const int wj = (tid & 15) * 8;   // W-load col

    unsigned long long acc[8][4];
#pragma unroll
    for (int i = 0; i < 8; i++)
#pragma unroll
        for (int jp = 0; jp < 4; jp++) acc[i][jp] = 0ULL;

    // ---------------- Layer 1: [TM x 384] @ [384 x 128] ----------------------
    const float* W1c = W1 + (size_t)c * (3 * H * H);
    for (int kt = 0; kt < 24; kt++) {
        int seg    = kt >> 3;              // 0: xs, 1: xe, 2: e
        int klocal = (kt & 7) * KT;
        const float* abase = (seg < 2) ? x : e;
        const float* asrc  = abase + sm.offs[seg][ar] + klocal + ak;
        float4 a0 = *reinterpret_cast<const float4*>(asrc);
        float4 a1 = *reinterpret_cast<const float4*>(asrc + 4);
        const float* wsrc = W1c + (size_t)(kt * KT + wk) * H + wj;
        float4 w0 = *reinterpret_cast<const float4*>(wsrc);
        float4 w1 = *reinterpret_cast<const float4*>(wsrc + 4);
        __syncthreads();  // previous tile fully consumed
        sm.As[ak + 0][ar] = a0.x; sm.As[ak + 1][ar] = a0.y;
        sm.As[ak + 2][ar] = a0.z; sm.As[ak + 3][ar] = a0.w;
        sm.As[ak + 4][ar] = a1.x; sm.As[ak + 5][ar] = a1.y;
        sm.As[ak + 6][ar] = a1.z; sm.As[ak + 7][ar] = a1.w;
        *reinterpret_cast<float4*>(&sm.Ws[wk][wj])     = w0;
        *reinterpret_cast<float4*>(&sm.Ws[wk][wj + 4]) = w1;
        __syncthreads();
#pragma unroll
        for (int k = 0; k < KT; k++) {
            float4 av0 = *reinterpret_cast<float4*>(&sm.As[k][ty * 8]);
            float4 av1 = *reinterpret_cast<float4*>(&sm.As[k][ty * 8 + 4]);
            float4 bv0 = *reinterpret_cast<float4*>(&sm.Ws[k][tx * 8]);
            float4 bv1 = *reinterpret_cast<float4*>(&sm.Ws[k][tx * 8 + 4]);
            unsigned long long bp0 = pack2(bv0.x, bv0.y);
            unsigned long long bp1 = pack2(bv0.z, bv0.w);
            unsigned long long bp2 = pack2(bv1.x, bv1.y);
            unsigned long long bp3 = pack2(bv1.z, bv1.w);
            float av[8] = {av0.x, av0.y, av0.z, av0.w, av1.x, av1.y, av1.z, av1.w};
#pragma unroll
            for (int i = 0; i < 8; i++) {
                unsigned long long ap = pack2(av[i], av[i]);
                ffma2(acc[i][0], ap, bp0);
                ffma2(acc[i][1], ap, bp1);
                ffma2(acc[i][2], ap, bp2);
                ffma2(acc[i][3], ap, bp3);
            }
        }
    }
    __syncthreads();
    {
        const float* b1c = b1 + c * H;
#pragma unroll
        for (int i = 0; i < 8; i++) {
            int r = ty * 8 + i;
#pragma unroll
            for (int jp = 0; jp < 4; jp++) {
                float lo, hi;
                unpack2(acc[i][jp], lo, hi);
                int j = tx * 8 + jp * 2;
                sm.h[r][j]     = lo + b1c[j];
                sm.h[r][j + 1] = hi + b1c[j + 1];
            }
        }
    }
    __syncthreads();
    ln_relu_row(sm, g1 + c * H, be1 + c * H, tid);
    __syncthreads();

    // ---------------- Layer 2: [TM x 128] @ [128 x 128] ----------------------
#pragma unroll
    for (int i = 0; i < 8; i++)
#pragma unroll
        for (int jp = 0; jp < 4; jp++) acc[i][jp] = 0ULL;

    const float* W2c = W2 + (size_t)c * H * H;
    for (int kt = 0; kt < 8; kt++) {
        const float* wsrc = W2c + (size_t)(kt * KT + wk) * H + wj;
        float4 w0 = *reinterpret_cast<const float4*>(wsrc);
        float4 w1 = *reinterpret_cast<const float4*>(wsrc + 4);
        __syncthreads();
        *reinterpret_cast<float4*>(&sm.Ws[wk][wj])     = w0;
        *reinterpret_cast<float4*>(&sm.Ws[wk][wj + 4]) = w1;
        __syncthreads();
#pragma unroll
        for (int k4 = 0; k4 < 4; k4++) {
            int kg = kt * KT + k4 * 4;
            float4 a[8];
#pragma unroll
            for (int i = 0; i < 8; i++)
                a[i] = *reinterpret_cast<float4*>(&sm.h[ty * 8 + i][kg]);
#pragma unroll
            for (int kk = 0; kk < 4; kk++) {
                int k = k4 * 4 + kk;
                float4 bv0 = *reinterpret_cast<float4*>(&sm.Ws[k][tx * 8]);
                float4 bv1 = *reinterpret_cast<float4*>(&sm.Ws[k][tx * 8 + 4]);
                unsigned long long bp0 = pack2(bv0.x, bv0.y);
                unsigned long long bp1 = pack2(bv0.z, bv0.w);
                unsigned long long bp2 = pack2(bv1.x, bv1.y);
                unsigned long long bp3 = pack2(bv1.z, bv1.w);
#pragma unroll
                for (int i = 0; i < 8; i++) {
                    float aval = (kk == 0) ? a[i].x : (kk == 1) ? a[i].y
                               : (kk == 2) ? a[i].z : a[i].w;
                    unsigned long long ap = pack2(aval, aval);
                    ffma2(acc[i][0], ap, bp0);
                    ffma2(acc[i][1], ap, bp1);
                    ffma2(acc[i][2], ap, bp2);
                    ffma2(acc[i][3], ap, bp3);
                }
            }
        }
    }
    __syncthreads();
    {
        const float* b2c = b2 + c * H;
#pragma unroll
        for (int i = 0; i < 8; i++) {
            int r = ty * 8 + i;
#pragma unroll
            for (int jp = 0; jp < 4; jp++) {
                float lo, hi;
                unpack2(acc[i][jp], lo, hi);
                int j = tx * 8 + jp * 2;
                sm.h[r][j]     = lo + b2c[j];
                sm.h[r][j + 1] = hi + b2c[j + 1];
            }
        }
    }
    __syncthreads();
    ln_relu_row(sm, g2 + c * H, be2 + c * H, tid);
    __syncthreads();

    // ---------------- Layer 3: [TM x 128] @ [128 x 1] -------------------------
    if (tid < m) {
        const float* w3  = W3 + c * H;
        float*       row = sm.h[tid];
        float s = 0.f;
#pragma unroll
        for (int q = 0; q < 32; q++) {
            float4 v = *reinterpret_cast<float4*>(row + q * 4);
            float4 w = *reinterpret_cast<const float4*>(w3 + q * 4);
            s += v.x * w.x + v.y * w.y + v.z * w.z + v.w * w.w;
        }
        out[sm.rowi[tid]] = s + b3[c];
    }
}

// ---------------- launch ------------------------------------------------------
extern "C" void kernel_launch(void* const* d_in, const int* in_sizes, int n_in,
                              void* d_out, int out_size) {
    const float* x   = (const float*)d_in[0];
    const int*   ei  = (const int*)d_in[1];
    const float* e   = (const float*)d_in[2];
    const int*   vol = (const int*)d_in[3];
    const float* W1  = (const float*)d_in[4];
    const float* b1  = (const float*)d_in[5];
    const float* g1  = (const float*)d_in[6];
    const float* be1 = (const float*)d_in[7];
    const float* W2  = (const float*)d_in[8];
    const float* b2  = (const float*)d_in[9];
    const float* g2  = (const float*)d_in[10];
    const float* be2 = (const float*)d_in[11];
    const float* W3  = (const float*)d_in[12];
    const float* b3  = (const float*)d_in[13];
    float* out = (float*)d_out;

    int E = in_sizes[1] / 2;   // edge_index is [2, E]
    if (E > MAXE) E = MAXE;

    cudaFuncSetAttribute(k_decode, cudaFuncAttributeMaxDynamicSharedMemorySize,
                         (int)sizeof(SMem));

    k_reset<<<1, 32>>>();
    int nb = (E + 255) / 256;
    k_classify<<<nb, 256>>>(ei, vol, out, E);
    k_prefix<<<1, 1>>>();
    k_scatter<<<nb, 256>>>(ei, vol, E);

    dim3 grid((E + TM - 1) / TM, 6);
    k_decode<<<grid, 256, sizeof(SMem)>>>(x, e, ei, W1, b1, g1, be1,
                                          W2, b2, g2, be2, W3, b3, out, E);
}

// round 3
// speedup vs baseline: 2.6049x; 2.6049x over previous
#include <cuda_runtime.h>
#include <cuda_fp16.h>
#include <cstdint>

#define H    128
#define MAXE 1000000
#define MAXN 100000

// ---------------- device globals -------------------------------------------
__device__ int    d_cnt[6];
__device__ int    d_perm6[6][MAXE];
// frag-packed weights: [c][kstep 0..31][ntile 0..15][lane 0..31] = {b0h,b1h,b0l,b1l}
__device__ uint4  d_wb[6 * 32 * 16 * 32];
__device__ __half d_xhi[MAXN * H];
__device__ __half d_xlo[MAXN * H];

__constant__ int c_lut[9] = {0, 1, 2, -1, 3, 4, -1, -1, 5};

// ---------------- helpers ----------------------------------------------------
__device__ __forceinline__ uint32_t h2bits(__half2 h) {
    return *reinterpret_cast<uint32_t*>(&h);
}
__device__ __forceinline__ void split2(float a, float b, uint32_t& hi, uint32_t& lo) {
    __half2 h = __floats2half2_rn(a, b);
    float2  r = __half22float2(h);
    __half2 l = __floats2half2_rn(a - r.x, b - r.y);
    hi = h2bits(h); lo = h2bits(l);
}
__device__ __forceinline__ void mma16816(float* d, const uint32_t* a,
                                         uint32_t b0, uint32_t b1) {
    asm volatile(
        "mma.sync.aligned.m16n8k16.row.col.f32.f16.f16.f32 "
        "{%0,%1,%2,%3}, {%4,%5,%6,%7}, {%8,%9}, {%0,%1,%2,%3};"
        : "+f"(d[0]), "+f"(d[1]), "+f"(d[2]), "+f"(d[3])
        : "r"(a[0]), "r"(a[1]), "r"(a[2]), "r"(a[3]), "r"(b0), "r"(b1));
}

// ---------------- bucketing ---------------------------------------------------
__global__ void k_reset() {
    if (threadIdx.x < 6) d_cnt[threadIdx.x] = 0;
}

__global__ void k_bucket(const int* __restrict__ ei, const int* __restrict__ vol,
                         float* __restrict__ out, int E) {
    __shared__ int cnt[6], base[6];
    int i = blockIdx.x * 256 + threadIdx.x;
    if (threadIdx.x < 6) cnt[threadIdx.x] = 0;
    __syncthreads();
    int c = -1, r = 0;
    if (i < E) {
        out[i] = 0.f;
        int gs = vol[ei[i]] / 3;
        int ge = vol[ei[E + i]] / 3;
        c = c_lut[gs * 3 + ge];
        if (c >= 0) r = atomicAdd(&cnt[c], 1);
    }
    __syncthreads();
    if (threadIdx.x < 6 && cnt[threadIdx.x] > 0)
        base[threadIdx.x] = atomicAdd(&d_cnt[threadIdx.x], cnt[threadIdx.x]);
    __syncthreads();
    if (c >= 0) d_perm6[c][base[c] + r] = i;
}

// ---------------- x pre-split --------------------------------------------------
__global__ void k_splitx(const float* __restrict__ x, int n4) {
    int i = blockIdx.x * 256 + threadIdx.x;
    if (i >= n4) return;
    float4 v = reinterpret_cast<const float4*>(x)[i];
    uint32_t h0, l0, h1, l1;
    split2(v.x, v.y, h0, l0);
    split2(v.z, v.w, h1, l1);
    reinterpret_cast<uint32_t*>(d_xhi)[i * 2]     = h0;
    reinterpret_cast<uint32_t*>(d_xhi)[i * 2 + 1] = h1;
    reinterpret_cast<uint32_t*>(d_xlo)[i * 2]     = l0;
    reinterpret_cast<uint32_t*>(d_xlo)[i * 2 + 1] = l1;
}

// ---------------- weight transform (frag-packed hi/lo) -------------------------
__global__ void k_transW(const float* __restrict__ W1, const float* __restrict__ W2) {
    int idx = blockIdx.x * 256 + threadIdx.x;     // 98304 total
    if (idx >= 6 * 32 * 16 * 32) return;
    int lane = idx & 31;
    int nt   = (idx >> 5) & 15;
    int ks   = (idx >> 9) & 31;
    int c    = idx >> 14;
    int gr = lane >> 2, tc = lane & 3;
    int n  = nt * 8 + gr;
    int k0 = ks * 16 + tc * 2;                    // global k (0..511)
    const float* Wsrc;
    int kk;
    if (ks < 24) { Wsrc = W1 + (size_t)c * 384 * 128; kk = k0; }
    else         { Wsrc = W2 + (size_t)c * 128 * 128; kk = k0 - 384; }
    float w00 = Wsrc[(size_t)kk * 128 + n];
    float w01 = Wsrc[(size_t)(kk + 1) * 128 + n];
    float w10 = Wsrc[(size_t)(kk + 8) * 128 + n];
    float w11 = Wsrc[(size_t)(kk + 9) * 128 + n];
    uint32_t b0h, b0l, b1h, b1l;
    split2(w00, w01, b0h, b0l);
    split2(w10, w11, b1h, b1l);
    d_wb[idx] = make_uint4(b0h, b1h, b0l, b1l);
}

// ---------------- smem layout ---------------------------------------------------
#define OFF_HHI  0         // 128 rows x 136 halves = 34816
#define OFF_HLO  34816
#define OFF_PAR  69632     // 896 floats
#define OFF_OFFS 73216     // 384 ints
#define OFF_ROWI 74752     // 128 ints
#define OFF_REDS 75264     // 256 floats
#define OFF_REDQ 76288
#define OFF_DOTS 77312
#define SMEM_BYTES 78336
#define HROW 272           // bytes per h row (136 halves)

// ---------------- fused decode ---------------------------------------------------
__global__ __launch_bounds__(256, 1) void k_decode(
    const float* __restrict__ e, const int* __restrict__ ei,
    const float* __restrict__ b1, const float* __restrict__ g1, const float* __restrict__ be1,
    const float* __restrict__ b2, const float* __restrict__ g2, const float* __restrict__ be2,
    const float* __restrict__ W3, const float* __restrict__ b3,
    float* __restrict__ out, int E) {
    extern __shared__ char smc[];

    const int c     = blockIdx.y;
    const int count = d_cnt[c];
    const int m0    = blockIdx.x * 128;
    if (m0 >= count) return;
    const int m   = min(128, count - m0);
    const int tid = threadIdx.x;

    float* par  = (float*)(smc + OFF_PAR);
    int*   offs = (int*)(smc + OFF_OFFS);
    int*   rowi = (int*)(smc + OFF_ROWI);
    float* reds = (float*)(smc + OFF_REDS);
    float* redq = (float*)(smc + OFF_REDQ);
    float* dots = (float*)(smc + OFF_DOTS);

    if (tid < 128) {
        par[tid]       = b1[c * H + tid];
        par[128 + tid] = g1[c * H + tid];
        par[256 + tid] = be1[c * H + tid];
        par[384 + tid] = b2[c * H + tid];
        par[512 + tid] = g2[c * H + tid];
        par[640 + tid] = be2[c * H + tid];
        par[768 + tid] = W3[c * H + tid];
        int rr = (tid < m) ? tid : 0;
        int i  = d_perm6[c][m0 + rr];
        rowi[tid] = i;
        offs[tid]       = ei[i] * H;
        offs[128 + tid] = ei[E + i] * H;
        offs[256 + tid] = i * H;
    }
    __syncthreads();

    const int wid   = tid >> 5;
    const int lane  = tid & 31;
    const int gr    = lane >> 2;
    const int tc    = lane & 3;
    const int slab  = (wid & 3) * 32;
    const int nhalf = wid >> 2;
    const int rA0 = slab + gr, rB0 = rA0 + 8, rA1 = rA0 + 16, rB1 = rA0 + 24;

    float acc[2][8][4];
#pragma unroll
    for (int mf = 0; mf < 2; mf++)
#pragma unroll
        for (int jt = 0; jt < 8; jt++)
#pragma unroll
            for (int u = 0; u < 4; u++) acc[mf][jt][u] = 0.f;

    const uint4* wbc = d_wb + ((size_t)c * 32 * 16 + nhalf * 8) * 32 + lane;

    // ================= Layer 1: K = 384 (segs x(s), x(t), e) ==================
#pragma unroll 1
    for (int seg = 0; seg < 2; seg++) {
        const __half* hA0 = d_xhi + offs[seg * 128 + rA0];
        const __half* hB0 = d_xhi + offs[seg * 128 + rB0];
        const __half* hA1 = d_xhi + offs[seg * 128 + rA1];
        const __half* hB1 = d_xhi + offs[seg * 128 + rB1];
        const __half* lA0 = d_xlo + offs[seg * 128 + rA0];
        const __half* lB0 = d_xlo + offs[seg * 128 + rB0];
        const __half* lA1 = d_xlo + offs[seg * 128 + rA1];
        const __half* lB1 = d_xlo + offs[seg * 128 + rB1];
#pragma unroll 1
        for (int ks8 = 0; ks8 < 8; ks8++) {
            int ks = seg * 8 + ks8;
            int k0 = ks8 * 16 + tc * 2, k1 = k0 + 8;
            uint32_t ah0[4], al0[4], ah1[4], al1[4];
            ah0[0] = *(const uint32_t*)(hA0 + k0); ah0[1] = *(const uint32_t*)(hB0 + k0);
            ah0[2] = *(const uint32_t*)(hA0 + k1); ah0[3] = *(const uint32_t*)(hB0 + k1);
            al0[0] = *(const uint32_t*)(lA0 + k0); al0[1] = *(const uint32_t*)(lB0 + k0);
            al0[2] = *(const uint32_t*)(lA0 + k1); al0[3] = *(const uint32_t*)(lB0 + k1);
            ah1[0] = *(const uint32_t*)(hA1 + k0); ah1[1] = *(const uint32_t*)(hB1 + k0);
            ah1[2] = *(const uint32_t*)(hA1 + k1); ah1[3] = *(const uint32_t*)(hB1 + k1);
            al1[0] = *(const uint32_t*)(lA1 + k0); al1[1] = *(const uint32_t*)(lB1 + k0);
            al1[2] = *(const uint32_t*)(lA1 + k1); al1[3] = *(const uint32_t*)(lB1 + k1);
            const uint4* bp = wbc + (size_t)ks * 16 * 32;
#pragma unroll
            for (int jt = 0; jt < 8; jt++) {
                uint4 b = bp[jt * 32];
                mma16816(acc[0][jt], ah0, b.x, b.y);
                mma16816(acc[0][jt], al0, b.x, b.y);
                mma16816(acc[0][jt], ah0, b.z, b.w);
                mma16816(acc[1][jt], ah1, b.x, b.y);
                mma16816(acc[1][jt], al1, b.x, b.y);
                mma16816(acc[1][jt], ah1, b.z, b.w);
            }
        }
    }
    {   // seg 2: e (fp32, split inline)
        const float* eA0 = e + offs[256 + rA0];
        const float* eB0 = e + offs[256 + rB0];
        const float* eA1 = e + offs[256 + rA1];
        const float* eB1 = e + offs[256 + rB1];
#pragma unroll 1
        for (int ks8 = 0; ks8 < 8; ks8++) {
            int ks = 16 + ks8;
            int k0 = ks8 * 16 + tc * 2, k1 = k0 + 8;
            uint32_t ah0[4], al0[4], ah1[4], al1[4];
            float2 v;
            v = *(const float2*)(eA0 + k0); split2(v.x, v.y, ah0[0], al0[0]);
            v = *(const float2*)(eB0 + k0); split2(v.x, v.y, ah0[1], al0[1]);
            v = *(const float2*)(eA0 + k1); split2(v.x, v.y, ah0[2], al0[2]);
            v = *(const float2*)(eB0 + k1); split2(v.x, v.y, ah0[3], al0[3]);
            v = *(const float2*)(eA1 + k0); split2(v.x, v.y, ah1[0], al1[0]);
            v = *(const float2*)(eB1 + k0); split2(v.x, v.y, ah1[1], al1[1]);
            v = *(const float2*)(eA1 + k1); split2(v.x, v.y, ah1[2], al1[2]);
            v = *(const float2*)(eB1 + k1); split2(v.x, v.y, ah1[3], al1[3]);
            const uint4* bp = wbc + (size_t)ks * 16 * 32;
#pragma unroll
            for (int jt = 0; jt < 8; jt++) {
                uint4 b = bp[jt * 32];
                mma16816(acc[0][jt], ah0, b.x, b.y);
                mma16816(acc[0][jt], al0, b.x, b.y);
                mma16816(acc[0][jt], ah0, b.z, b.w);
                mma16816(acc[1][jt], ah1, b.x, b.y);
                mma16816(acc[1][jt], al1, b.x, b.y);
                mma16816(acc[1][jt], ah1, b.z, b.w);
            }
        }
    }

    // ---------------- epilogue 1: bias + LN + ReLU -> smem h (hi/lo fp16) -----
    {
        float sA[2] = {0, 0}, qA[2] = {0, 0}, sB[2] = {0, 0}, qB[2] = {0, 0};
#pragma unroll
        for (int mf = 0; mf < 2; mf++)
#pragma unroll
            for (int jt = 0; jt < 8; jt++) {
                int col = nhalf * 64 + jt * 8 + tc * 2;
                float2 bb = *(const float2*)(par + col);
                float v0 = acc[mf][jt][0] + bb.x, v1 = acc[mf][jt][1] + bb.y;
                float v2 = acc[mf][jt][2] + bb.x, v3 = acc[mf][jt][3] + bb.y;
                acc[mf][jt][0] = v0; acc[mf][jt][1] = v1;
                acc[mf][jt][2] = v2; acc[mf][jt][3] = v3;
                sA[mf] += v0 + v1; qA[mf] += v0 * v0 + v1 * v1;
                sB[mf] += v2 + v3; qB[mf] += v2 * v2 + v3 * v3;
            }
#pragma unroll
        for (int d = 1; d < 4; d <<= 1) {
            sA[0] += __shfl_xor_sync(~0u, sA[0], d); qA[0] += __shfl_xor_sync(~0u, qA[0], d);
            sB[0] += __shfl_xor_sync(~0u, sB[0], d); qB[0] += __shfl_xor_sync(~0u, qB[0], d);
            sA[1] += __shfl_xor_sync(~0u, sA[1], d); qA[1] += __shfl_xor_sync(~0u, qA[1], d);
            sB[1] += __shfl_xor_sync(~0u, sB[1], d); qB[1] += __shfl_xor_sync(~0u, qB[1], d);
        }
        if (tc == 0) {
            reds[rA0 * 2 + nhalf] = sA[0]; redq[rA0 * 2 + nhalf] = qA[0];
            reds[rB0 * 2 + nhalf] = sB[0]; redq[rB0 * 2 + nhalf] = qB[0];
            reds[rA1 * 2 + nhalf] = sA[1]; redq[rA1 * 2 + nhalf] = qA[1];
            reds[rB1 * 2 + nhalf] = sB[1]; redq[rB1 * 2 + nhalf] = qB[1];
        }
        __syncthreads();
        int   rw[4] = {rA0, rB0, rA1, rB1};
        float mu[4], iv[4];
#pragma unroll
        for (int u = 0; u < 4; u++) {
            float st = reds[rw[u] * 2] + reds[rw[u] * 2 + 1];
            float qt = redq[rw[u] * 2] + redq[rw[u] * 2 + 1];
            mu[u] = st * (1.f / 128.f);
            iv[u] = rsqrtf(qt * (1.f / 128.f) - mu[u] * mu[u] + 1e-5f);
        }
#pragma unroll
        for (int mf = 0; mf < 2; mf++)
#pragma unroll
            for (int jt = 0; jt < 8; jt++) {
                int col = nhalf * 64 + jt * 8 + tc * 2;
                float2 gg = *(const float2*)(par + 128 + col);
                float2 ee = *(const float2*)(par + 256 + col);
                int ua = mf * 2, ub = mf * 2 + 1;
                float h0 = fmaxf((acc[mf][jt][0] - mu[ua]) * iv[ua] * gg.x + ee.x, 0.f);
                float h1 = fmaxf((acc[mf][jt][1] - mu[ua]) * iv[ua] * gg.y + ee.y, 0.f);
                float h2 = fmaxf((acc[mf][jt][2] - mu[ub]) * iv[ub] * gg.x + ee.x, 0.f);
                float h3 = fmaxf((acc[mf][jt][3] - mu[ub]) * iv[ub] * gg.y + ee.y, 0.f);
                uint32_t hh, hl;
                split2(h0, h1, hh, hl);
                *(uint32_t*)(smc + OFF_HHI + rw[ua] * HROW + col * 2) = hh;
                *(uint32_t*)(smc + OFF_HLO + rw[ua] * HROW + col * 2) = hl;
                split2(h2, h3, hh, hl);
                *(uint32_t*)(smc + OFF_HHI + rw[ub] * HROW + col * 2) = hh;
                *(uint32_t*)(smc + OFF_HLO + rw[ub] * HROW + col * 2) = hl;
            }
    }
    __syncthreads();

    // ================= Layer 2: K = 128, A from smem h =========================
#pragma unroll
    for (int mf = 0; mf < 2; mf++)
#pragma unroll
        for (int jt = 0; jt < 8; jt++)
#pragma unroll
            for (int u = 0; u < 4; u++) acc[mf][jt][u] = 0.f;

#pragma unroll 1
    for (int ks8 = 0; ks8 < 8; ks8++) {
        int ks = 24 + ks8;
        int k0 = ks8 * 16 + tc * 2, k1 = k0 + 8;
        uint32_t ah0[4], al0[4], ah1[4], al1[4];
        ah0[0] = *(uint32_t*)(smc + OFF_HHI + rA0 * HROW + k0 * 2);
        ah0[1] = *(uint32_t*)(smc + OFF_HHI + rB0 * HROW + k0 * 2);
        ah0[2] = *(uint32_t*)(smc + OFF_HHI + rA0 * HROW + k1 * 2);
        ah0[3] = *(uint32_t*)(smc + OFF_HHI + rB0 * HROW + k1 * 2);
        al0[0] = *(uint32_t*)(smc + OFF_HLO + rA0 * HROW + k0 * 2);
        al0[1] = *(uint32_t*)(smc + OFF_HLO + rB0 * HROW + k0 * 2);
        al0[2] = *(uint32_t*)(smc + OFF_HLO + rA0 * HROW + k1 * 2);
        al0[3] = *(uint32_t*)(smc + OFF_HLO + rB0 * HROW + k1 * 2);
        ah1[0] = *(uint32_t*)(smc + OFF_HHI + rA1 * HROW + k0 * 2);
        ah1[1] = *(uint32_t*)(smc + OFF_HHI + rB1 * HROW + k0 * 2);
        ah1[2] = *(uint32_t*)(smc + OFF_HHI + rA1 * HROW + k1 * 2);
        ah1[3] = *(uint32_t*)(smc + OFF_HHI + rB1 * HROW + k1 * 2);
        al1[0] = *(uint32_t*)(smc + OFF_HLO + rA1 * HROW + k0 * 2);
        al1[1] = *(uint32_t*)(smc + OFF_HLO + rB1 * HROW + k0 * 2);
        al1[2] = *(uint32_t*)(smc + OFF_HLO + rA1 * HROW + k1 * 2);
        al1[3] = *(uint32_t*)(smc + OFF_HLO + rB1 * HROW + k1 * 2);
        const uint4* bp = wbc + (size_t)ks * 16 * 32;
#pragma unroll
        for (int jt = 0; jt < 8; jt++) {
            uint4 b = bp[jt * 32];
            mma16816(acc[0][jt], ah0, b.x, b.y);
            mma16816(acc[0][jt], al0, b.x, b.y);
            mma16816(acc[0][jt], ah0, b.z, b.w);
            mma16816(acc[1][jt], ah1, b.x, b.y);
            mma16816(acc[1][jt], al1, b.x, b.y);
            mma16816(acc[1][jt], ah1, b.z, b.w);
        }
    }

    // ---------------- epilogue 2: bias + LN + ReLU + layer-3 dot ---------------
    {
        float sA[2] = {0, 0}, qA[2] = {0, 0}, sB[2] = {0, 0}, qB[2] = {0, 0};
#pragma unroll
        for (int mf = 0; mf < 2; mf++)
#pragma unroll
            for (int jt = 0; jt < 8; jt++) {
                int col = nhalf * 64 + jt * 8 + tc * 2;
                float2 bb = *(const float2*)(par + 384 + col);
                float v0 = acc[mf][jt][0] + bb.x, v1 = acc[mf][jt][1] + bb.y;
                float v2 = acc[mf][jt][2] + bb.x, v3 = acc[mf][jt][3] + bb.y;
                acc[mf][jt][0] = v0; acc[mf][jt][1] = v1;
                acc[mf][jt][2] = v2; acc[mf][jt][3] = v3;
                sA[mf] += v0 + v1; qA[mf] += v0 * v0 + v1 * v1;
                sB[mf] += v2 + v3; qB[mf] += v2 * v2 + v3 * v3;
            }
#pragma unroll
        for (int d = 1; d < 4; d <<= 1) {
            sA[0] += __shfl_xor_sync(~0u, sA[0], d); qA[0] += __shfl_xor_sync(~0u, qA[0], d);
            sB[0] += __shfl_xor_sync(~0u, sB[0], d); qB[0] += __shfl_xor_sync(~0u, qB[0], d);
            sA[1] += __shfl_xor_sync(~0u, sA[1], d); qA[1] += __shfl_xor_sync(~0u, qA[1], d);
            sB[1] += __shfl_xor_sync(~0u, sB[1], d); qB[1] += __shfl_xor_sync(~0u, qB[1], d);
        }
        __syncthreads();   // protect reds/redq reuse
        if (tc == 0) {
            reds[rA0 * 2 + nhalf] = sA[0]; redq[rA0 * 2 + nhalf] = qA[0];
            reds[rB0 * 2 + nhalf] = sB[0]; redq[rB0 * 2 + nhalf] = qB[0];
            reds[rA1 * 2 + nhalf] = sA[1]; redq[rA1 * 2 + nhalf] = qA[1];
            reds[rB1 * 2 + nhalf] = sB[1]; redq[rB1 * 2 + nhalf] = qB[1];
        }
        __syncthreads();
        int   rw[4] = {rA0, rB0, rA1, rB1};
        float mu[4], iv[4], dt[4] = {0, 0, 0, 0};
#pragma unroll
        for (int u = 0; u < 4; u++) {
            float st = reds[rw[u] * 2] + reds[rw[u] * 2 + 1];
            float qt = redq[rw[u] * 2] + redq[rw[u] * 2 + 1];
            mu[u] = st * (1.f / 128.f);
            iv[u] = rsqrtf(qt * (1.f / 128.f) - mu[u] * mu[u] + 1e-5f);
        }
#pragma unroll
        for (int mf = 0; mf < 2; mf++)
#pragma unroll
            for (int jt = 0; jt < 8; jt++) {
                int col = nhalf * 64 + jt * 8 + tc * 2;
                float2 gg = *(const float2*)(par + 512 + col);
                float2 ee = *(const float2*)(par + 640 + col);
                float2 ww = *(const float2*)(par + 768 + col);
                int ua = mf * 2, ub = mf * 2 + 1;
                float h0 = fmaxf((acc[mf][jt][0] - mu[ua]) * iv[ua] * gg.x + ee.x, 0.f);
                float h1 = fmaxf((acc[mf][jt][1] - mu[ua]) * iv[ua] * gg.y + ee.y, 0.f);
                float h2 = fmaxf((acc[mf][jt][2] - mu[ub]) * iv[ub] * gg.x + ee.x, 0.f);
                float h3 = fmaxf((acc[mf][jt][3] - mu[ub]) * iv[ub] * gg.y + ee.y, 0.f);
                dt[ua] += h0 * ww.x + h1 * ww.y;
                dt[ub] += h2 * ww.x + h3 * ww.y;
            }
#pragma unroll
        for (int d = 1; d < 4; d <<= 1) {
            dt[0] += __shfl_xor_sync(~0u, dt[0], d);
            dt[1] += __shfl_xor_sync(~0u, dt[1], d);
            dt[2] += __shfl_xor_sync(~0u, dt[2], d);
            dt[3] += __shfl_xor_sync(~0u, dt[3], d);
        }
        if (tc == 0) {
#pragma unroll
            for (int u = 0; u < 4; u++) dots[rw[u] * 2 + nhalf] = dt[u];
        }
        __syncthreads();
        if (tid < m)
            out[rowi[tid]] = dots[tid * 2] + dots[tid * 2 + 1] + b3[c];
    }
}

// ---------------- launch ----------------------------------------------------------
extern "C" void kernel_launch(void* const* d_in, const int* in_sizes, int n_in,
                              void* d_out, int out_size) {
    const float* x   = (const float*)d_in[0];
    const int*   ei  = (const int*)d_in[1];
    const float* e   = (const float*)d_in[2];
    const int*   vol = (const int*)d_in[3];
    const float* W1  = (const float*)d_in[4];
    const float* b1  = (const float*)d_in[5];
    const float* g1  = (const float*)d_in[6];
    const float* be1 = (const float*)d_in[7];
    const float* W2  = (const float*)d_in[8];
    const float* b2  = (const float*)d_in[9];
    const float* g2  = (const float*)d_in[10];
    const float* be2 = (const float*)d_in[11];
    const float* W3  = (const float*)d_in[12];
    const float* b3  = (const float*)d_in[13];
    float* out = (float*)d_out;

    int E = in_sizes[1] / 2;
    if (E > MAXE) E = MAXE;
    int N = in_sizes[0] / H;
    if (N > MAXN) N = MAXN;

    cudaFuncSetAttribute(k_decode, cudaFuncAttributeMaxDynamicSharedMemorySize, SMEM_BYTES);

    k_reset<<<1, 32>>>();
    k_bucket<<<(E + 255) / 256, 256>>>(ei, vol, out, E);
    int n4 = N * (H / 4);
    k_splitx<<<(n4 + 255) / 256, 256>>>(x, n4);
    k_transW<<<(6 * 32 * 16 * 32 + 255) / 256, 256>>>(W1, W2);

    dim3 grid((E + 127) / 128, 6);
    k_decode<<<grid, 256, SMEM_BYTES>>>(e, ei, b1, g1, be1, b2, g2, be2,
                                        W3, b3, out, E);
}

// round 4
// speedup vs baseline: 3.6821x; 1.4135x over previous
#include <cuda_runtime.h>
#include <cuda_fp16.h>
#include <cstdint>

#define H    128
#define MAXE 1000000

// ---------------- device globals -------------------------------------------
__device__ int   d_cnt[6];
__device__ int   d_perm6[6][MAXE];
// frag-packed fp16 weights: [c][kstep 0..31][ntile 0..15][lane 0..31] = {b0,b1}
__device__ uint2 d_wb[6 * 32 * 16 * 32];

__constant__ int c_lut[9] = {0, 1, 2, -1, 3, 4, -1, -1, 5};

// ---------------- helpers ----------------------------------------------------
__device__ __forceinline__ uint32_t smem_u32(const void* p) {
    uint32_t a;
    asm("{ .reg .u64 t; cvta.to.shared.u64 t, %1; cvt.u32.u64 %0, t; }" : "=r"(a) : "l"(p));
    return a;
}
__device__ __forceinline__ uint32_t h2bits(__half2 h) {
    return *reinterpret_cast<uint32_t*>(&h);
}
__device__ __forceinline__ void split2(float a, float b, uint32_t& hi, uint32_t& lo) {
    __half2 h = __floats2half2_rn(a, b);
    float2  r = __half22float2(h);
    __half2 l = __floats2half2_rn(a - r.x, b - r.y);
    hi = h2bits(h); lo = h2bits(l);
}
__device__ __forceinline__ void mma16816(float* d, const uint32_t* a,
                                         uint32_t b0, uint32_t b1) {
    asm volatile(
        "mma.sync.aligned.m16n8k16.row.col.f32.f16.f16.f32 "
        "{%0,%1,%2,%3}, {%4,%5,%6,%7}, {%8,%9}, {%0,%1,%2,%3};"
        : "+f"(d[0]), "+f"(d[1]), "+f"(d[2]), "+f"(d[3])
        : "r"(a[0]), "r"(a[1]), "r"(a[2]), "r"(a[3]), "r"(b0), "r"(b1));
}
__device__ __forceinline__ void ldsm4(uint32_t* r, uint32_t addr) {
    asm volatile("ldmatrix.sync.aligned.m8n8.x4.shared.b16 {%0,%1,%2,%3}, [%4];"
                 : "=r"(r[0]), "=r"(r[1]), "=r"(r[2]), "=r"(r[3]) : "r"(addr));
}

// ---------------- bucketing ---------------------------------------------------
__global__ void k_reset() {
    if (threadIdx.x < 6) d_cnt[threadIdx.x] = 0;
}

__global__ void k_bucket(const int* __restrict__ ei, const int* __restrict__ vol,
                         float* __restrict__ out, int E) {
    __shared__ int cnt[6], base[6];
    int i = blockIdx.x * 256 + threadIdx.x;
    if (threadIdx.x < 6) cnt[threadIdx.x] = 0;
    __syncthreads();
    int c = -1, r = 0;
    if (i < E) {
        out[i] = 0.f;
        int gs = vol[ei[i]] / 3;
        int ge = vol[ei[E + i]] / 3;
        c = c_lut[gs * 3 + ge];
        if (c >= 0) r = atomicAdd(&cnt[c], 1);
    }
    __syncthreads();
    if (threadIdx.x < 6 && cnt[threadIdx.x] > 0)
        base[threadIdx.x] = atomicAdd(&d_cnt[threadIdx.x], cnt[threadIdx.x]);
    __syncthreads();
    if (c >= 0) d_perm6[c][base[c] + r] = i;
}

// ---------------- weight transform (frag-packed fp16) -------------------------
__global__ void k_transW(const float* __restrict__ W1, const float* __restrict__ W2) {
    int idx = blockIdx.x * 256 + threadIdx.x;     // 98304 total
    if (idx >= 6 * 32 * 16 * 32) return;
    int lane = idx & 31;
    int nt   = (idx >> 5) & 15;
    int ks   = (idx >> 9) & 31;
    int c    = idx >> 14;
    int gr = lane >> 2, tc = lane & 3;
    int n  = nt * 8 + gr;
    int k0 = ks * 16 + tc * 2;                    // global k (0..511)
    const float* Wsrc;
    int kk;
    if (ks < 24) { Wsrc = W1 + (size_t)c * 384 * 128; kk = k0; }
    else         { Wsrc = W2 + (size_t)c * 128 * 128; kk = k0 - 384; }
    float w00 = Wsrc[(size_t)kk * 128 + n];
    float w01 = Wsrc[(size_t)(kk + 1) * 128 + n];
    float w10 = Wsrc[(size_t)(kk + 8) * 128 + n];
    float w11 = Wsrc[(size_t)(kk + 9) * 128 + n];
    uint32_t b0 = h2bits(__floats2half2_rn(w00, w01));
    uint32_t b1 = h2bits(__floats2half2_rn(w10, w11));
    d_wb[idx] = make_uint2(b0, b1);
}

// ---------------- smem layout ---------------------------------------------------
#define BUF_HI   0         // 128 rows x 136 halves (272B stride) = 34816
#define BUF_LO   34816
#define OFF_PAR  69632     // 896 floats
#define OFF_OFFS 73216     // 384 ints
#define OFF_ROWI 74752     // 128 ints
#define OFF_REDS 75264     // 256 floats
#define OFF_REDQ 76288
#define OFF_DOTS 77312
#define SMEM_BYTES 78336
#define HROW 272           // bytes per staged row (136 halves)

// ---------------- fused decode ---------------------------------------------------
__global__ __launch_bounds__(256, 2) void k_decode(
    const float* __restrict__ x, const float* __restrict__ e, const int* __restrict__ ei,
    const float* __restrict__ b1, const float* __restrict__ g1, const float* __restrict__ be1,
    const float* __restrict__ b2, const float* __restrict__ g2, const float* __restrict__ be2,
    const float* __restrict__ W3, const float* __restrict__ b3,
    float* __restrict__ out, int E) {
    extern __shared__ char smc[];

    const int c     = blockIdx.y;
    const int count = d_cnt[c];
    const int m0    = blockIdx.x * 128;
    if (m0 >= count) return;
    const int m   = min(128, count - m0);
    const int tid = threadIdx.x;

    float* par  = (float*)(smc + OFF_PAR);
    int*   offs = (int*)(smc + OFF_OFFS);
    int*   rowi = (int*)(smc + OFF_ROWI);
    float* reds = (float*)(smc + OFF_REDS);
    float* redq = (float*)(smc + OFF_REDQ);
    float* dots = (float*)(smc + OFF_DOTS);

    if (tid < 128) {
        par[tid]       = b1[c * H + tid];
        par[128 + tid] = g1[c * H + tid];
        par[256 + tid] = be1[c * H + tid];
        par[384 + tid] = b2[c * H + tid];
        par[512 + tid] = g2[c * H + tid];
        par[640 + tid] = be2[c * H + tid];
        par[768 + tid] = W3[c * H + tid];
        int rr = (tid < m) ? tid : 0;
        int i  = d_perm6[c][m0 + rr];
        rowi[tid] = i;
        offs[tid]       = ei[i] * H;
        offs[128 + tid] = ei[E + i] * H;
        offs[256 + tid] = i * H;
    }
    __syncthreads();

    const int wid   = tid >> 5;
    const int lane  = tid & 31;
    const int gr    = lane >> 2;
    const int tc    = lane & 3;
    const int slab  = (wid & 3) * 32;
    const int nhalf = wid >> 2;
    const int rA0 = slab + gr, rB0 = rA0 + 8, rA1 = rA0 + 16, rB1 = rA0 + 24;

    // ldmatrix lane base addresses (16-row a-frag tiles, hi/lo buffers)
    const uint32_t sb   = smem_u32(smc);
    const int      lrow = lane & 15;
    const int      lcol = lane >> 4;
    const uint32_t aH0 = sb + BUF_HI + (uint32_t)(slab + lrow) * HROW + lcol * 16;
    const uint32_t aL0 = sb + BUF_LO + (uint32_t)(slab + lrow) * HROW + lcol * 16;
    const uint32_t aH1 = aH0 + 16 * HROW;
    const uint32_t aL1 = aL0 + 16 * HROW;

    float acc[2][8][4];
#pragma unroll
    for (int mf = 0; mf < 2; mf++)
#pragma unroll
        for (int jt = 0; jt < 8; jt++)
#pragma unroll
            for (int u = 0; u < 4; u++) acc[mf][jt][u] = 0.f;

    const uint2* wbc = d_wb + ((size_t)c * 32 * 16 + nhalf * 8) * 32 + lane;

    // ================= Layer 1: 3 segs (xs, xe, e), K=384 =====================
#pragma unroll 1
    for (int seg = 0; seg < 3; seg++) {
        const float* basep = (seg == 2) ? e : x;
        __syncthreads();   // staged buffer free (prev seg consumed)
        // stage 128 gathered fp32 rows -> smem fp16 hi/lo (coalesced)
#pragma unroll 1
        for (int it = 0; it < 16; it++) {
            int r = it * 8 + wid;
            const float* src = basep + offs[seg * 128 + r] + lane * 4;
            float4 v = *reinterpret_cast<const float4*>(src);
            uint32_t h0, l0, h1, l1;
            split2(v.x, v.y, h0, l0);
            split2(v.z, v.w, h1, l1);
            *(uint2*)(smc + BUF_HI + r * HROW + lane * 8) = make_uint2(h0, h1);
            *(uint2*)(smc + BUF_LO + r * HROW + lane * 8) = make_uint2(l0, l1);
        }
        __syncthreads();
#pragma unroll 1
        for (int ks8 = 0; ks8 < 8; ks8++) {
            uint32_t ah0[4], al0[4], ah1[4], al1[4];
            ldsm4(ah0, aH0 + ks8 * 32);
            ldsm4(al0, aL0 + ks8 * 32);
            ldsm4(ah1, aH1 + ks8 * 32);
            ldsm4(al1, aL1 + ks8 * 32);
            const uint2* bp = wbc + (size_t)(seg * 8 + ks8) * 16 * 32;
#pragma unroll
            for (int jt = 0; jt < 8; jt++) {
                uint2 b = bp[jt * 32];
                mma16816(acc[0][jt], ah0, b.x, b.y);
                mma16816(acc[0][jt], al0, b.x, b.y);
                mma16816(acc[1][jt], ah1, b.x, b.y);
                mma16816(acc[1][jt], al1, b.x, b.y);
            }
        }
    }

    // ---------------- epilogue 1: bias + LN + ReLU -> smem h (hi/lo fp16) -----
    {
        float sA[2] = {0, 0}, qA[2] = {0, 0}, sB[2] = {0, 0}, qB[2] = {0, 0};
#pragma unroll
        for (int mf = 0; mf < 2; mf++)
#pragma unroll
            for (int jt = 0; jt < 8; jt++) {
                int col = nhalf * 64 + jt * 8 + tc * 2;
                float2 bb = *(const float2*)(par + col);
                float v0 = acc[mf][jt][0] + bb.x, v1 = acc[mf][jt][1] + bb.y;
                float v2 = acc[mf][jt][2] + bb.x, v3 = acc[mf][jt][3] + bb.y;
                acc[mf][jt][0] = v0; acc[mf][jt][1] = v1;
                acc[mf][jt][2] = v2; acc[mf][jt][3] = v3;
                sA[mf] += v0 + v1; qA[mf] += v0 * v0 + v1 * v1;
                sB[mf] += v2 + v3; qB[mf] += v2 * v2 + v3 * v3;
            }
#pragma unroll
        for (int d = 1; d < 4; d <<= 1) {
            sA[0] += __shfl_xor_sync(~0u, sA[0], d); qA[0] += __shfl_xor_sync(~0u, qA[0], d);
            sB[0] += __shfl_xor_sync(~0u, sB[0], d); qB[0] += __shfl_xor_sync(~0u, qB[0], d);
            sA[1] += __shfl_xor_sync(~0u, sA[1], d); qA[1] += __shfl_xor_sync(~0u, qA[1], d);
            sB[1] += __shfl_xor_sync(~0u, sB[1], d); qB[1] += __shfl_xor_sync(~0u, qB[1], d);
        }
        if (tc == 0) {
            reds[rA0 * 2 + nhalf] = sA[0]; redq[rA0 * 2 + nhalf] = qA[0];
            reds[rB0 * 2 + nhalf] = sB[0]; redq[rB0 * 2 + nhalf] = qB[0];
            reds[rA1 * 2 + nhalf] = sA[1]; redq[rA1 * 2 + nhalf] = qA[1];
            reds[rB1 * 2 + nhalf] = sB[1]; redq[rB1 * 2 + nhalf] = qB[1];
        }
        __syncthreads();
        int   rw[4] = {rA0, rB0, rA1, rB1};
        float mu[4], iv[4];
#pragma unroll
        for (int u = 0; u < 4; u++) {
            float st = reds[rw[u] * 2] + reds[rw[u] * 2 + 1];
            float qt = redq[rw[u] * 2] + redq[rw[u] * 2 + 1];
            mu[u] = st * (1.f / 128.f);
            iv[u] = rsqrtf(qt * (1.f / 128.f) - mu[u] * mu[u] + 1e-5f);
        }
#pragma unroll
        for (int mf = 0; mf < 2; mf++)
#pragma unroll
            for (int jt = 0; jt < 8; jt++) {
                int col = nhalf * 64 + jt * 8 + tc * 2;
                float2 gg = *(const float2*)(par + 128 + col);
                float2 ee = *(const float2*)(par + 256 + col);
                int ua = mf * 2, ub = mf * 2 + 1;
                float h0 = fmaxf((acc[mf][jt][0] - mu[ua]) * iv[ua] * gg.x + ee.x, 0.f);
                float h1 = fmaxf((acc[mf][jt][1] - mu[ua]) * iv[ua] * gg.y + ee.y, 0.f);
                float h2 = fmaxf((acc[mf][jt][2] - mu[ub]) * iv[ub] * gg.x + ee.x, 0.f);
                float h3 = fmaxf((acc[mf][jt][3] - mu[ub]) * iv[ub] * gg.y + ee.y, 0.f);
                uint32_t hh, hl;
                split2(h0, h1, hh, hl);
                *(uint32_t*)(smc + BUF_HI + rw[ua] * HROW + col * 2) = hh;
                *(uint32_t*)(smc + BUF_LO + rw[ua] * HROW + col * 2) = hl;
                split2(h2, h3, hh, hl);
                *(uint32_t*)(smc + BUF_HI + rw[ub] * HROW + col * 2) = hh;
                *(uint32_t*)(smc + BUF_LO + rw[ub] * HROW + col * 2) = hl;
            }
    }
    __syncthreads();

    // ================= Layer 2: K = 128, A = h from smem =======================
#pragma unroll
    for (int mf = 0; mf < 2; mf++)
#pragma unroll
        for (int jt = 0; jt < 8; jt++)
#pragma unroll
            for (int u = 0; u < 4; u++) acc[mf][jt][u] = 0.f;

#pragma unroll 1
    for (int ks8 = 0; ks8 < 8; ks8++) {
        uint32_t ah0[4], al0[4], ah1[4], al1[4];
        ldsm4(ah0, aH0 + ks8 * 32);
        ldsm4(al0, aL0 + ks8 * 32);
        ldsm4(ah1, aH1 + ks8 * 32);
        ldsm4(al1, aL1 + ks8 * 32);
        const uint2* bp = wbc + (size_t)(24 + ks8) * 16 * 32;
#pragma unroll
        for (int jt = 0; jt < 8; jt++) {
            uint2 b = bp[jt * 32];
            mma16816(acc[0][jt], ah0, b.x, b.y);
            mma16816(acc[0][jt], al0, b.x, b.y);
            mma16816(acc[1][jt], ah1, b.x, b.y);
            mma16816(acc[1][jt], al1, b.x, b.y);
        }
    }

    // ---------------- epilogue 2: bias + LN + ReLU + layer-3 dot ---------------
    {
        float sA[2] = {0, 0}, qA[2] = {0, 0}, sB[2] = {0, 0}, qB[2] = {0, 0};
#pragma unroll
        for (int mf = 0; mf < 2; mf++)
#pragma unroll
            for (int jt = 0; jt < 8; jt++) {
                int col = nhalf * 64 + jt * 8 + tc * 2;
                float2 bb = *(const float2*)(par + 384 + col);
                float v0 = acc[mf][jt][0] + bb.x, v1 = acc[mf][jt][1] + bb.y;
                float v2 = acc[mf][jt][2] + bb.x, v3 = acc[mf][jt][3] + bb.y;
                acc[mf][jt][0] = v0; acc[mf][jt][1] = v1;
                acc[mf][jt][2] = v2; acc[mf][jt][3] = v3;
                sA[mf] += v0 + v1; qA[mf] += v0 * v0 + v1 * v1;
                sB[mf] += v2 + v3; qB[mf] += v2 * v2 + v3 * v3;
            }
#pragma unroll
        for (int d = 1; d < 4; d <<= 1) {
            sA[0] += __shfl_xor_sync(~0u, sA[0], d); qA[0] += __shfl_xor_sync(~0u, qA[0], d);
            sB[0] += __shfl_xor_sync(~0u, sB[0], d); qB[0] += __shfl_xor_sync(~0u, qB[0], d);
            sA[1] += __shfl_xor_sync(~0u, sA[1], d); qA[1] += __shfl_xor_sync(~0u, qA[1], d);
            sB[1] += __shfl_xor_sync(~0u, sB[1], d); qB[1] += __shfl_xor_sync(~0u, qB[1], d);
        }
        __syncthreads();   // protect reds/redq reuse
        if (tc == 0) {
            reds[rA0 * 2 + nhalf] = sA[0]; redq[rA0 * 2 + nhalf] = qA[0];
            reds[rB0 * 2 + nhalf] = sB[0]; redq[rB0 * 2 + nhalf] = qB[0];
            reds[rA1 * 2 + nhalf] = sA[1]; redq[rA1 * 2 + nhalf] = qA[1];
            reds[rB1 * 2 + nhalf] = sB[1]; redq[rB1 * 2 + nhalf] = qB[1];
        }
        __syncthreads();
        int   rw[4] = {rA0, rB0, rA1, rB1};
        float mu[4], iv[4], dt[4] = {0, 0, 0, 0};
#pragma unroll
        for (int u = 0; u < 4; u++) {
            float st = reds[rw[u] * 2] + reds[rw[u] * 2 + 1];
            float qt = redq[rw[u] * 2] + redq[rw[u] * 2 + 1];
            mu[u] = st * (1.f / 128.f);
            iv[u] = rsqrtf(qt * (1.f / 128.f) - mu[u] * mu[u] + 1e-5f);
        }
#pragma unroll
        for (int mf = 0; mf < 2; mf++)
#pragma unroll
            for (int jt = 0; jt < 8; jt++) {
                int col = nhalf * 64 + jt * 8 + tc * 2;
                float2 gg = *(const float2*)(par + 512 + col);
                float2 ee = *(const float2*)(par + 640 + col);
                float2 ww = *(const float2*)(par + 768 + col);
                int ua = mf * 2, ub = mf * 2 + 1;
                float h0 = fmaxf((acc[mf][jt][0] - mu[ua]) * iv[ua] * gg.x + ee.x, 0.f);
                float h1 = fmaxf((acc[mf][jt][1] - mu[ua]) * iv[ua] * gg.y + ee.y, 0.f);
                float h2 = fmaxf((acc[mf][jt][2] - mu[ub]) * iv[ub] * gg.x + ee.x, 0.f);
                float h3 = fmaxf((acc[mf][jt][3] - mu[ub]) * iv[ub] * gg.y + ee.y, 0.f);
                dt[ua] += h0 * ww.x + h1 * ww.y;
                dt[ub] += h2 * ww.x + h3 * ww.y;
            }
#pragma unroll
        for (int d = 1; d < 4; d <<= 1) {
            dt[0] += __shfl_xor_sync(~0u, dt[0], d);
            dt[1] += __shfl_xor_sync(~0u, dt[1], d);
            dt[2] += __shfl_xor_sync(~0u, dt[2], d);
            dt[3] += __shfl_xor_sync(~0u, dt[3], d);
        }
        if (tc == 0) {
#pragma unroll
            for (int u = 0; u < 4; u++) dots[rw[u] * 2 + nhalf] = dt[u];
        }
        __syncthreads();
        if (tid < m)
            out[rowi[tid]] = dots[tid * 2] + dots[tid * 2 + 1] + b3[c];
    }
}

// ---------------- launch ----------------------------------------------------------
extern "C" void kernel_launch(void* const* d_in, const int* in_sizes, int n_in,
                              void* d_out, int out_size) {
    const float* x   = (const float*)d_in[0];
    const int*   ei  = (const int*)d_in[1];
    const float* e   = (const float*)d_in[2];
    const int*   vol = (const int*)d_in[3];
    const float* W1  = (const float*)d_in[4];
    const float* b1  = (const float*)d_in[5];
    const float* g1  = (const float*)d_in[6];
    const float* be1 = (const float*)d_in[7];
    const float* W2  = (const float*)d_in[8];
    const float* b2  = (const float*)d_in[9];
    const float* g2  = (const float*)d_in[10];
    const float* be2 = (const float*)d_in[11];
    const float* W3  = (const float*)d_in[12];
    const float* b3  = (const float*)d_in[13];
    float* out = (float*)d_out;

    int E = in_sizes[1] / 2;
    if (E > MAXE) E = MAXE;

    cudaFuncSetAttribute(k_decode, cudaFuncAttributeMaxDynamicSharedMemorySize, SMEM_BYTES);

    k_reset<<<1, 32>>>();
    k_bucket<<<(E + 255) / 256, 256>>>(ei, vol, out, E);
    k_transW<<<(6 * 32 * 16 * 32 + 255) / 256, 256>>>(W1, W2);

    dim3 grid((E + 127) / 128, 6);
    k_decode<<<grid, 256, SMEM_BYTES>>>(x, e, ei, b1, g1, be1, b2, g2, be2,
                                        W3, b3, out, E);
}

// round 5
// speedup vs baseline: 4.5250x; 1.2289x over previous
#include <cuda_runtime.h>
#include <cuda_fp16.h>
#include <cstdint>

#define H    128
#define MAXE 1000000

// ---------------- device globals -------------------------------------------
__device__ int   d_cnt[6];
__device__ int   d_toff[7];
__device__ int   d_perm6[6][MAXE];
// frag-packed fp16 weights: [c][kstep 0..31][ntile 0..15][lane 0..31] = {b0,b1}
__device__ uint2 d_wb[6 * 32 * 16 * 32];

__constant__ int c_lut[9] = {0, 1, 2, -1, 3, 4, -1, -1, 5};

// ---------------- helpers ----------------------------------------------------
__device__ __forceinline__ uint32_t smem_u32(const void* p) {
    uint32_t a;
    asm("{ .reg .u64 t; cvta.to.shared.u64 t, %1; cvt.u32.u64 %0, t; }" : "=r"(a) : "l"(p));
    return a;
}
__device__ __forceinline__ uint32_t h2bits(__half2 h) {
    return *reinterpret_cast<uint32_t*>(&h);
}
__device__ __forceinline__ void mma16816(float* d, const uint32_t* a,
                                         uint32_t b0, uint32_t b1) {
    asm volatile(
        "mma.sync.aligned.m16n8k16.row.col.f32.f16.f16.f32 "
        "{%0,%1,%2,%3}, {%4,%5,%6,%7}, {%8,%9}, {%0,%1,%2,%3};"
        : "+f"(d[0]), "+f"(d[1]), "+f"(d[2]), "+f"(d[3])
        : "r"(a[0]), "r"(a[1]), "r"(a[2]), "r"(a[3]), "r"(b0), "r"(b1));
}
__device__ __forceinline__ void ldsm4(uint32_t* r, uint32_t addr) {
    asm volatile("ldmatrix.sync.aligned.m8n8.x4.shared.b16 {%0,%1,%2,%3}, [%4];"
                 : "=r"(r[0]), "=r"(r[1]), "=r"(r[2]), "=r"(r[3]) : "r"(addr));
}

// ---------------- bucketing ---------------------------------------------------
__global__ void k_reset() {
    if (threadIdx.x < 6) d_cnt[threadIdx.x] = 0;
}

__global__ void k_bucket(const int* __restrict__ ei, const int* __restrict__ vol,
                         float* __restrict__ out, int E) {
    __shared__ int cnt[6], base[6];
    int i = blockIdx.x * 256 + threadIdx.x;
    if (threadIdx.x < 6) cnt[threadIdx.x] = 0;
    __syncthreads();
    int c = -1, r = 0;
    if (i < E) {
        out[i] = 0.f;
        int gs = vol[ei[i]] / 3;
        int ge = vol[ei[E + i]] / 3;
        c = c_lut[gs * 3 + ge];
        if (c >= 0) r = atomicAdd(&cnt[c], 1);
    }
    __syncthreads();
    if (threadIdx.x < 6 && cnt[threadIdx.x] > 0)
        base[threadIdx.x] = atomicAdd(&d_cnt[threadIdx.x], cnt[threadIdx.x]);
    __syncthreads();
    if (c >= 0) d_perm6[c][base[c] + r] = i;
}

__global__ void k_prefix() {
    if (threadIdx.x == 0) {
        int o = 0;
        for (int c = 0; c < 6; c++) { d_toff[c] = o; o += (d_cnt[c] + 127) >> 7; }
        d_toff[6] = o;
    }
}

// ---------------- weight transform (frag-packed fp16) -------------------------
__global__ void k_transW(const float* __restrict__ W1, const float* __restrict__ W2) {
    int idx = blockIdx.x * 256 + threadIdx.x;     // 98304 total
    if (idx >= 6 * 32 * 16 * 32) return;
    int lane = idx & 31;
    int nt   = (idx >> 5) & 15;
    int ks   = (idx >> 9) & 31;
    int c    = idx >> 14;
    int gr = lane >> 2, tc = lane & 3;
    int n  = nt * 8 + gr;
    int k0 = ks * 16 + tc * 2;                    // global k (0..511)
    const float* Wsrc;
    int kk;
    if (ks < 24) { Wsrc = W1 + (size_t)c * 384 * 128; kk = k0; }
    else         { Wsrc = W2 + (size_t)c * 128 * 128; kk = k0 - 384; }
    float w00 = Wsrc[(size_t)kk * 128 + n];
    float w01 = Wsrc[(size_t)(kk + 1) * 128 + n];
    float w10 = Wsrc[(size_t)(kk + 8) * 128 + n];
    float w11 = Wsrc[(size_t)(kk + 9) * 128 + n];
    uint32_t b0 = h2bits(__floats2half2_rn(w00, w01));
    uint32_t b1 = h2bits(__floats2half2_rn(w10, w11));
    d_wb[idx] = make_uint2(b0, b1);
}

// ---------------- smem layout ---------------------------------------------------
#define BUF_HI   0         // 128 rows x 136 halves (272B stride) = 34816
#define OFF_PAR  34816     // 896 floats
#define OFF_OFFS 38400     // 384 ints
#define OFF_ROWI 39936     // 128 ints
#define OFF_REDS 40448     // 256 floats
#define OFF_REDQ 41472
#define OFF_DOTS 42496
#define SMEM_BYTES 43520
#define HROW 272           // bytes per staged row (136 halves)

// ---------------- fused decode ---------------------------------------------------
__global__ __launch_bounds__(256, 2) void k_decode(
    const float* __restrict__ x, const float* __restrict__ e, const int* __restrict__ ei,
    const float* __restrict__ b1, const float* __restrict__ g1, const float* __restrict__ be1,
    const float* __restrict__ b2, const float* __restrict__ g2, const float* __restrict__ be2,
    const float* __restrict__ W3, const float* __restrict__ b3,
    float* __restrict__ out, int E) {
    extern __shared__ char smc[];

    // ---- flattened grid: block -> (combo, tile) ----
    const int b = blockIdx.x;
    if (b >= d_toff[6]) return;
    int c = 0;
#pragma unroll
    for (int q = 1; q < 6; q++) c += (b >= d_toff[q]);
    const int count = d_cnt[c];
    const int m0    = (b - d_toff[c]) * 128;
    const int m     = min(128, count - m0);
    const int tid   = threadIdx.x;

    float* par  = (float*)(smc + OFF_PAR);
    int*   offs = (int*)(smc + OFF_OFFS);
    int*   rowi = (int*)(smc + OFF_ROWI);
    float* reds = (float*)(smc + OFF_REDS);
    float* redq = (float*)(smc + OFF_REDQ);
    float* dots = (float*)(smc + OFF_DOTS);

    if (tid < 128) {
        par[tid]       = b1[c * H + tid];
        par[128 + tid] = g1[c * H + tid];
        par[256 + tid] = be1[c * H + tid];
        par[384 + tid] = b2[c * H + tid];
        par[512 + tid] = g2[c * H + tid];
        par[640 + tid] = be2[c * H + tid];
        par[768 + tid] = W3[c * H + tid];
        int rr = (tid < m) ? tid : 0;
        int i  = d_perm6[c][m0 + rr];
        rowi[tid] = i;
        offs[tid]       = ei[i] * H;
        offs[128 + tid] = ei[E + i] * H;
        offs[256 + tid] = i * H;
    }
    __syncthreads();

    const int wid   = tid >> 5;
    const int lane  = tid & 31;
    const int gr    = lane >> 2;
    const int tc    = lane & 3;
    const int slab  = (wid & 3) * 32;
    const int nhalf = wid >> 2;
    const int rA0 = slab + gr, rB0 = rA0 + 8, rA1 = rA0 + 16, rB1 = rA0 + 24;

    // ldmatrix lane base addresses (16-row a-frag tiles)
    const uint32_t sb   = smem_u32(smc);
    const int      lrow = lane & 15;
    const int      lcol = lane >> 4;
    const uint32_t aH0 = sb + BUF_HI + (uint32_t)(slab + lrow) * HROW + lcol * 16;
    const uint32_t aH1 = aH0 + 16 * HROW;

    float acc[2][8][4];
#pragma unroll
    for (int mf = 0; mf < 2; mf++)
#pragma unroll
        for (int jt = 0; jt < 8; jt++)
#pragma unroll
            for (int u = 0; u < 4; u++) acc[mf][jt][u] = 0.f;

    const uint2* wbc = d_wb + ((size_t)c * 32 * 16 + nhalf * 8) * 32 + lane;

    // ================= Layer 1: 3 segs (xs, xe, e), K=384 =====================
#pragma unroll 1
    for (int seg = 0; seg < 3; seg++) {
        const float* basep = (seg == 2) ? e : x;
        __syncthreads();   // staged buffer free (prev seg consumed)
        // stage 128 gathered fp32 rows -> smem fp16 (coalesced)
#pragma unroll 1
        for (int it = 0; it < 16; it++) {
            int r = it * 8 + wid;
            const float* src = basep + offs[seg * 128 + r] + lane * 4;
            float4 v = *reinterpret_cast<const float4*>(src);
            uint32_t h0 = h2bits(__floats2half2_rn(v.x, v.y));
            uint32_t h1 = h2bits(__floats2half2_rn(v.z, v.w));
            *(uint2*)(smc + BUF_HI + r * HROW + lane * 8) = make_uint2(h0, h1);
        }
        __syncthreads();
#pragma unroll 1
        for (int ks8 = 0; ks8 < 8; ks8++) {
            uint32_t ah0[4], ah1[4];
            ldsm4(ah0, aH0 + ks8 * 32);
            ldsm4(ah1, aH1 + ks8 * 32);
            const uint2* bp = wbc + (size_t)(seg * 8 + ks8) * 16 * 32;
#pragma unroll
            for (int jt = 0; jt < 8; jt++) {
                uint2 b2f = bp[jt * 32];
                mma16816(acc[0][jt], ah0, b2f.x, b2f.y);
                mma16816(acc[1][jt], ah1, b2f.x, b2f.y);
            }
        }
    }

    // ---------------- epilogue 1: bias + LN + ReLU -> smem h (fp16) ------------
    {
        float sA[2] = {0, 0}, qA[2] = {0, 0}, sB[2] = {0, 0}, qB[2] = {0, 0};
#pragma unroll
        for (int mf = 0; mf < 2; mf++)
#pragma unroll
            for (int jt = 0; jt < 8; jt++) {
                int col = nhalf * 64 + jt * 8 + tc * 2;
                float2 bb = *(const float2*)(par + col);
                float v0 = acc[mf][jt][0] + bb.x, v1 = acc[mf][jt][1] + bb.y;
                float v2 = acc[mf][jt][2] + bb.x, v3 = acc[mf][jt][3] + bb.y;
                acc[mf][jt][0] = v0; acc[mf][jt][1] = v1;
                acc[mf][jt][2] = v2; acc[mf][jt][3] = v3;
                sA[mf] += v0 + v1; qA[mf] += v0 * v0 + v1 * v1;
                sB[mf] += v2 + v3; qB[mf] += v2 * v2 + v3 * v3;
            }
#pragma unroll
        for (int d = 1; d < 4; d <<= 1) {
            sA[0] += __shfl_xor_sync(~0u, sA[0], d); qA[0] += __shfl_xor_sync(~0u, qA[0], d);
            sB[0] += __shfl_xor_sync(~0u, sB[0], d); qB[0] += __shfl_xor_sync(~0u, qB[0], d);
            sA[1] += __shfl_xor_sync(~0u, sA[1], d); qA[1] += __shfl_xor_sync(~0u, qA[1], d);
            sB[1] += __shfl_xor_sync(~0u, sB[1], d); qB[1] += __shfl_xor_sync(~0u, qB[1], d);
        }
        if (tc == 0) {
            reds[rA0 * 2 + nhalf] = sA[0]; redq[rA0 * 2 + nhalf] = qA[0];
            reds[rB0 * 2 + nhalf] = sB[0]; redq[rB0 * 2 + nhalf] = qB[0];
            reds[rA1 * 2 + nhalf] = sA[1]; redq[rA1 * 2 + nhalf] = qA[1];
            reds[rB1 * 2 + nhalf] = sB[1]; redq[rB1 * 2 + nhalf] = qB[1];
        }
        __syncthreads();
        int   rw[4] = {rA0, rB0, rA1, rB1};
        float mu[4], iv[4];
#pragma unroll
        for (int u = 0; u < 4; u++) {
            float st = reds[rw[u] * 2] + reds[rw[u] * 2 + 1];
            float qt = redq[rw[u] * 2] + redq[rw[u] * 2 + 1];
            mu[u] = st * (1.f / 128.f);
            iv[u] = rsqrtf(qt * (1.f / 128.f) - mu[u] * mu[u] + 1e-5f);
        }
#pragma unroll
        for (int mf = 0; mf < 2; mf++)
#pragma unroll
            for (int jt = 0; jt < 8; jt++) {
                int col = nhalf * 64 + jt * 8 + tc * 2;
                float2 gg = *(const float2*)(par + 128 + col);
                float2 ee = *(const float2*)(par + 256 + col);
                int ua = mf * 2, ub = mf * 2 + 1;
                float h0 = fmaxf((acc[mf][jt][0] - mu[ua]) * iv[ua] * gg.x + ee.x, 0.f);
                float h1 = fmaxf((acc[mf][jt][1] - mu[ua]) * iv[ua] * gg.y + ee.y, 0.f);
                float h2 = fmaxf((acc[mf][jt][2] - mu[ub]) * iv[ub] * gg.x + ee.x, 0.f);
                float h3 = fmaxf((acc[mf][jt][3] - mu[ub]) * iv[ub] * gg.y + ee.y, 0.f);
                *(uint32_t*)(smc + BUF_HI + rw[ua] * HROW + col * 2) =
                    h2bits(__floats2half2_rn(h0, h1));
                *(uint32_t*)(smc + BUF_HI + rw[ub] * HROW + col * 2) =
                    h2bits(__floats2half2_rn(h2, h3));
            }
    }
    __syncthreads();

    // ================= Layer 2: K = 128, A = h from smem =======================
#pragma unroll
    for (int mf = 0; mf < 2; mf++)
#pragma unroll
        for (int jt = 0; jt < 8; jt++)
#pragma unroll
            for (int u = 0; u < 4; u++) acc[mf][jt][u] = 0.f;

#pragma unroll 1
    for (int ks8 = 0; ks8 < 8; ks8++) {
        uint32_t ah0[4], ah1[4];
        ldsm4(ah0, aH0 + ks8 * 32);
        ldsm4(ah1, aH1 + ks8 * 32);
        const uint2* bp = wbc + (size_t)(24 + ks8) * 16 * 32;
#pragma unroll
        for (int jt = 0; jt < 8; jt++) {
            uint2 b2f = bp[jt * 32];
            mma16816(acc[0][jt], ah0, b2f.x, b2f.y);
            mma16816(acc[1][jt], ah1, b2f.x, b2f.y);
        }
    }

    // ---------------- epilogue 2: bias + LN + ReLU + layer-3 dot ---------------
    {
        float sA[2] = {0, 0}, qA[2] = {0, 0}, sB[2] = {0, 0}, qB[2] = {0, 0};
#pragma unroll
        for (int mf = 0; mf < 2; mf++)
#pragma unroll
            for (int jt = 0; jt < 8; jt++) {
                int col = nhalf * 64 + jt * 8 + tc * 2;
                float2 bb = *(const float2*)(par + 384 + col);
                float v0 = acc[mf][jt][0] + bb.x, v1 = acc[mf][jt][1] + bb.y;
                float v2 = acc[mf][jt][2] + bb.x, v3 = acc[mf][jt][3] + bb.y;
                acc[mf][jt][0] = v0; acc[mf][jt][1] = v1;
                acc[mf][jt][2] = v2; acc[mf][jt][3] = v3;
                sA[mf] += v0 + v1; qA[mf] += v0 * v0 + v1 * v1;
                sB[mf] += v2 + v3; qB[mf] += v2 * v2 + v3 * v3;
            }
#pragma unroll
        for (int d = 1; d < 4; d <<= 1) {
            sA[0] += __shfl_xor_sync(~0u, sA[0], d); qA[0] += __shfl_xor_sync(~0u, qA[0], d);
            sB[0] += __shfl_xor_sync(~0u, sB[0], d); qB[0] += __shfl_xor_sync(~0u, qB[0], d);
            sA[1] += __shfl_xor_sync(~0u, sA[1], d); qA[1] += __shfl_xor_sync(~0u, qA[1], d);
            sB[1] += __shfl_xor_sync(~0u, sB[1], d); qB[1] += __shfl_xor_sync(~0u, qB[1], d);
        }
        __syncthreads();   // protect reds/redq reuse
        if (tc == 0) {
            reds[rA0 * 2 + nhalf] = sA[0]; redq[rA0 * 2 + nhalf] = qA[0];
            reds[rB0 * 2 + nhalf] = sB[0]; redq[rB0 * 2 + nhalf] = qB[0];
            reds[rA1 * 2 + nhalf] = sA[1]; redq[rA1 * 2 + nhalf] = qA[1];
            reds[rB1 * 2 + nhalf] = sB[1]; redq[rB1 * 2 + nhalf] = qB[1];
        }
        __syncthreads();
        int   rw[4] = {rA0, rB0, rA1, rB1};
        float mu[4], iv[4], dt[4] = {0, 0, 0, 0};
#pragma unroll
        for (int u = 0; u < 4; u++) {
            float st = reds[rw[u] * 2] + reds[rw[u] * 2 + 1];
            float qt = redq[rw[u] * 2] + redq[rw[u] * 2 + 1];
            mu[u] = st * (1.f / 128.f);
            iv[u] = rsqrtf(qt * (1.f / 128.f) - mu[u] * mu[u] + 1e-5f);
        }
#pragma unroll
        for (int mf = 0; mf < 2; mf++)
#pragma unroll
            for (int jt = 0; jt < 8; jt++) {
                int col = nhalf * 64 + jt * 8 + tc * 2;
                float2 gg = *(const float2*)(par + 512 + col);
                float2 ee = *(const float2*)(par + 640 + col);
                float2 ww = *(const float2*)(par + 768 + col);
                int ua = mf * 2, ub = mf * 2 + 1;
                float h0 = fmaxf((acc[mf][jt][0] - mu[ua]) * iv[ua] * gg.x + ee.x, 0.f);
                float h1 = fmaxf((acc[mf][jt][1] - mu[ua]) * iv[ua] * gg.y + ee.y, 0.f);
                float h2 = fmaxf((acc[mf][jt][2] - mu[ub]) * iv[ub] * gg.x + ee.x, 0.f);
                float h3 = fmaxf((acc[mf][jt][3] - mu[ub]) * iv[ub] * gg.y + ee.y, 0.f);
                dt[ua] += h0 * ww.x + h1 * ww.y;
                dt[ub] += h2 * ww.x + h3 * ww.y;
            }
#pragma unroll
        for (int d = 1; d < 4; d <<= 1) {
            dt[0] += __shfl_xor_sync(~0u, dt[0], d);
            dt[1] += __shfl_xor_sync(~0u, dt[1], d);
            dt[2] += __shfl_xor_sync(~0u, dt[2], d);
            dt[3] += __shfl_xor_sync(~0u, dt[3], d);
        }
        if (tc == 0) {
#pragma unroll
            for (int u = 0; u < 4; u++) dots[rw[u] * 2 + nhalf] = dt[u];
        }
        __syncthreads();
        if (tid < m)
            out[rowi[tid]] = dots[tid * 2] + dots[tid * 2 + 1] + b3[c];
    }
}

// ---------------- launch ----------------------------------------------------------
extern "C" void kernel_launch(void* const* d_in, const int* in_sizes, int n_in,
                              void* d_out, int out_size) {
    const float* x   = (const float*)d_in[0];
    const int*   ei  = (const int*)d_in[1];
    const float* e   = (const float*)d_in[2];
    const int*   vol = (const int*)d_in[3];
    const float* W1  = (const float*)d_in[4];
    const float* b1  = (const float*)d_in[5];
    const float* g1  = (const float*)d_in[6];
    const float* be1 = (const float*)d_in[7];
    const float* W2  = (const float*)d_in[8];
    const float* b2  = (const float*)d_in[9];
    const float* g2  = (const float*)d_in[10];
    const float* be2 = (const float*)d_in[11];
    const float* W3  = (const float*)d_in[12];
    const float* b3  = (const float*)d_in[13];
    float* out = (float*)d_out;

    int E = in_sizes[1] / 2;
    if (E > MAXE) E = MAXE;

    cudaFuncSetAttribute(k_decode, cudaFuncAttributeMaxDynamicSharedMemorySize, SMEM_BYTES);

    k_reset<<<1, 32>>>();
    k_bucket<<<(E + 255) / 256, 256>>>(ei, vol, out, E);
    k_prefix<<<1, 1>>>();
    k_transW<<<(6 * 32 * 16 * 32 + 255) / 256, 256>>>(W1, W2);

    int gx = (E + 127) / 128 + 6;
    k_decode<<<gx, 256, SMEM_BYTES>>>(x, e, ei, b1, g1, be1, b2, g2, be2,
                                      W3, b3, out, E);
}